// round 1
// baseline (speedup 1.0000x reference)
#include <cuda_runtime.h>
#include <math.h>
#include <stdint.h>

#define NBATCH 8
#define NNB    4096
#define NTOT   32768
#define EDG    65536
#define HID    512

// ---------------- scratch (device globals; no allocs allowed) ----------------
__device__ float g_H1[(size_t)NTOT * HID];      // 64 MB   (also reused for G = silu(H2@Wh1+bh1))
__device__ float g_P [(size_t)NTOT * 1024];     // 128 MB  (cols 0:512 = H1@W2_0, 512:1024 = H1@W2_1)
__device__ float g_H2[(size_t)NTOT * HID];      // 64 MB
__device__ int   g_cnt[NNB];
__device__ int   g_rowptr[NNB + 1];
__device__ int   g_csr_src[EDG];
__device__ float g_csr_norm[EDG];
__device__ float g_dinv[NNB];

__device__ __forceinline__ float siluf(float x) {
    return x / (1.0f + expf(-x));
}

// ---------------- CSR build ----------------
__global__ void zero_cnt_kernel() {
    int i = blockIdx.x * blockDim.x + threadIdx.x;
    if (i < NNB) g_cnt[i] = 0;
}

__global__ void hist_kernel(const int* __restrict__ ei) {
    int e = blockIdx.x * blockDim.x + threadIdx.x;
    if (e < EDG) atomicAdd(&g_cnt[ei[EDG + e]], 1);
}

// one block, 1024 threads: dinv, exclusive scan of counts -> rowptr, reset cursors
__global__ void scan_kernel() {
    __shared__ int s[1024];
    int tid = threadIdx.x;
    int c0 = g_cnt[tid * 4 + 0];
    int c1 = g_cnt[tid * 4 + 1];
    int c2 = g_cnt[tid * 4 + 2];
    int c3 = g_cnt[tid * 4 + 3];
    int local = c0 + c1 + c2 + c3;
    s[tid] = local;
    __syncthreads();
    for (int off = 1; off < 1024; off <<= 1) {
        int t = (tid >= off) ? s[tid - off] : 0;
        __syncthreads();
        s[tid] += t;
        __syncthreads();
    }
    int incl = s[tid];
    int excl = incl - local;
    g_rowptr[tid * 4 + 0] = excl;
    g_rowptr[tid * 4 + 1] = excl + c0;
    g_rowptr[tid * 4 + 2] = excl + c0 + c1;
    g_rowptr[tid * 4 + 3] = excl + c0 + c1 + c2;
    if (tid == 1023) g_rowptr[NNB] = incl;
    // degree includes the self-loop (+1)
    g_dinv[tid * 4 + 0] = rsqrtf((float)(c0 + 1));
    g_dinv[tid * 4 + 1] = rsqrtf((float)(c1 + 1));
    g_dinv[tid * 4 + 2] = rsqrtf((float)(c2 + 1));
    g_dinv[tid * 4 + 3] = rsqrtf((float)(c3 + 1));
    // reset cursors for scatter
    g_cnt[tid * 4 + 0] = 0;
    g_cnt[tid * 4 + 1] = 0;
    g_cnt[tid * 4 + 2] = 0;
    g_cnt[tid * 4 + 3] = 0;
}

__global__ void scatter_kernel(const int* __restrict__ ei) {
    int e = blockIdx.x * blockDim.x + threadIdx.x;
    if (e >= EDG) return;
    int s = ei[e];
    int d = ei[EDG + e];
    int pos = g_rowptr[d] + atomicAdd(&g_cnt[d], 1);
    g_csr_src[pos]  = s;
    g_csr_norm[pos] = g_dinv[s] * g_dinv[d];
}

// ---------------- layer 1: H1 = silu(x@W1_0 + agg(x)@W1_1 + b1_0 + b1_1) ----------------
// one warp per node; weights (2x512 twice) + bias sum in smem
__global__ void layer1_kernel(const float* __restrict__ X,
                              const float* __restrict__ W10, const float* __restrict__ b10,
                              const float* __restrict__ W11, const float* __restrict__ b11) {
    __shared__ float sW[5 * HID]; // [0]:W10 r0, [512]:W10 r1, [1024]:W11 r0, [1536]:W11 r1, [2048]:bias sum
    int tid = threadIdx.x;
    for (int i = tid; i < HID; i += 256) {
        sW[i]             = W10[i];
        sW[HID + i]       = W10[HID + i];
        sW[2 * HID + i]   = W11[i];
        sW[3 * HID + i]   = W11[HID + i];
        sW[4 * HID + i]   = b10[i] + b11[i];
    }
    __syncthreads();

    int warp = tid >> 5, lane = tid & 31;
    int n = blockIdx.x * 8 + warp;
    int v = n & (NNB - 1);
    int base = n & ~(NNB - 1);

    float x0 = X[2 * n], x1 = X[2 * n + 1];
    float a0 = 0.f, a1 = 0.f;
    int r0 = g_rowptr[v], r1 = g_rowptr[v + 1];
    for (int e = r0 + lane; e < r1; e += 32) {
        int s = g_csr_src[e];
        float nm = g_csr_norm[e];
        a0 += nm * X[2 * (base + s)];
        a1 += nm * X[2 * (base + s) + 1];
    }
#pragma unroll
    for (int off = 16; off; off >>= 1) {
        a0 += __shfl_down_sync(0xffffffffu, a0, off);
        a1 += __shfl_down_sync(0xffffffffu, a1, off);
    }
    a0 = __shfl_sync(0xffffffffu, a0, 0);
    a1 = __shfl_sync(0xffffffffu, a1, 0);
    float dv = g_dinv[v];
    float sn = dv * dv;
    a0 += sn * x0;
    a1 += sn * x1;

    float* out = &g_H1[(size_t)n * HID];
#pragma unroll 4
    for (int j = lane; j < HID; j += 32) {
        float h = x0 * sW[j] + x1 * sW[HID + j] + a0 * sW[2 * HID + j] + a1 * sW[3 * HID + j] + sW[4 * HID + j];
        out[j] = siluf(h);
    }
}

// ---------------- fp32 tiled GEMM: C = A(MxK) @ B(KxN), optional bias+silu epilogue ----------------
// BM=BN=128, BK=16, 256 threads, 8x8 per thread, double-buffered smem
template <int MODE>  // 0: plain store, 1: silu(acc + bias[col])
__global__ void __launch_bounds__(256, 2)
sgemm_kernel(const float* __restrict__ A, const float* __restrict__ B,
             float* __restrict__ C, const float* __restrict__ bias,
             int M, int N, int K, int lda, int ldb, int ldc) {
    __shared__ float As[2][16][128];
    __shared__ float Bs[2][16][128];

    int tid = threadIdx.x;
    int bx = blockIdx.x, by = blockIdx.y;

    const float* Aptr = A + (size_t)(by * 128) * lda;
    const float* Bptr = B + (size_t)(bx * 128);

    int aRow0 = tid >> 2,          aK0 = (tid & 3) * 4;
    int aRow1 = (tid + 256) >> 2,  aK1 = aK0;  // ((tid+256)&3)==(tid&3)
    int bK0   = tid >> 5,          bCol0 = (tid & 31) * 4;
    int bK1   = bK0 + 8,           bCol1 = bCol0;

    float acc[8][8];
#pragma unroll
    for (int i = 0; i < 8; i++)
#pragma unroll
        for (int j = 0; j < 8; j++) acc[i][j] = 0.f;

    float4 va0, va1, vb0, vb1;

    // prologue: load tile 0
    {
        const float* Ak = Aptr;
        va0 = *(const float4*)(Ak + (size_t)aRow0 * lda + aK0);
        va1 = *(const float4*)(Ak + (size_t)aRow1 * lda + aK1);
        const float* Bk = Bptr;
        vb0 = *(const float4*)(Bk + (size_t)bK0 * ldb + bCol0);
        vb1 = *(const float4*)(Bk + (size_t)bK1 * ldb + bCol1);
        As[0][aK0 + 0][aRow0] = va0.x; As[0][aK0 + 1][aRow0] = va0.y;
        As[0][aK0 + 2][aRow0] = va0.z; As[0][aK0 + 3][aRow0] = va0.w;
        As[0][aK1 + 0][aRow1] = va1.x; As[0][aK1 + 1][aRow1] = va1.y;
        As[0][aK1 + 2][aRow1] = va1.z; As[0][aK1 + 3][aRow1] = va1.w;
        *(float4*)&Bs[0][bK0][bCol0] = vb0;
        *(float4*)&Bs[0][bK1][bCol1] = vb1;
    }
    __syncthreads();

    int tRow = (tid >> 4) * 8;
    int tCol = (tid & 15) * 8;
    int nt = K / 16;

    for (int t = 0; t < nt; t++) {
        int cur = t & 1;
        if (t + 1 < nt) {
            const float* Ak = Aptr + (t + 1) * 16;
            va0 = *(const float4*)(Ak + (size_t)aRow0 * lda + aK0);
            va1 = *(const float4*)(Ak + (size_t)aRow1 * lda + aK1);
            const float* Bk = Bptr + (size_t)((t + 1) * 16) * ldb;
            vb0 = *(const float4*)(Bk + (size_t)bK0 * ldb + bCol0);
            vb1 = *(const float4*)(Bk + (size_t)bK1 * ldb + bCol1);
        }
#pragma unroll
        for (int k = 0; k < 16; k++) {
            float4 a0 = *(float4*)&As[cur][k][tRow];
            float4 a1 = *(float4*)&As[cur][k][tRow + 4];
            float4 b0 = *(float4*)&Bs[cur][k][tCol];
            float4 b1 = *(float4*)&Bs[cur][k][tCol + 4];
            float ra[8] = {a0.x, a0.y, a0.z, a0.w, a1.x, a1.y, a1.z, a1.w};
            float rb[8] = {b0.x, b0.y, b0.z, b0.w, b1.x, b1.y, b1.z, b1.w};
#pragma unroll
            for (int i = 0; i < 8; i++)
#pragma unroll
                for (int j = 0; j < 8; j++) acc[i][j] += ra[i] * rb[j];
        }
        if (t + 1 < nt) {
            int nxt = cur ^ 1;
            As[nxt][aK0 + 0][aRow0] = va0.x; As[nxt][aK0 + 1][aRow0] = va0.y;
            As[nxt][aK0 + 2][aRow0] = va0.z; As[nxt][aK0 + 3][aRow0] = va0.w;
            As[nxt][aK1 + 0][aRow1] = va1.x; As[nxt][aK1 + 1][aRow1] = va1.y;
            As[nxt][aK1 + 2][aRow1] = va1.z; As[nxt][aK1 + 3][aRow1] = va1.w;
            *(float4*)&Bs[nxt][bK0][bCol0] = vb0;
            *(float4*)&Bs[nxt][bK1][bCol1] = vb1;
        }
        __syncthreads();
    }

    float bs[8];
    if (MODE == 1) {
#pragma unroll
        for (int j = 0; j < 8; j++) bs[j] = bias[bx * 128 + tCol + j];
    }

    float* Cptr = C + (size_t)(by * 128) * ldc + bx * 128;
#pragma unroll
    for (int i = 0; i < 8; i++) {
        int row = tRow + i;
#pragma unroll
        for (int jj = 0; jj < 8; jj += 4) {
            float4 v;
            v.x = acc[i][jj + 0];
            v.y = acc[i][jj + 1];
            v.z = acc[i][jj + 2];
            v.w = acc[i][jj + 3];
            if (MODE == 1) {
                v.x = siluf(v.x + bs[jj + 0]);
                v.y = siluf(v.y + bs[jj + 1]);
                v.z = siluf(v.z + bs[jj + 2]);
                v.w = siluf(v.w + bs[jj + 3]);
            }
            *(float4*)(Cptr + (size_t)row * ldc + tCol + jj) = v;
        }
    }
}

// ---------------- layer 2 combine: H2 = silu(P[:, :512] + agg(P[:, 512:]) + b2_0 + b2_1) ----------------
// one block (128 threads) per node; thread handles 4 consecutive features (float4)
__global__ void agg2_kernel(const float* __restrict__ b20, const float* __restrict__ b21) {
    int n = blockIdx.x;
    int tid = threadIdx.x;
    int v = n & (NNB - 1);
    int base = n & ~(NNB - 1);
    int j = tid * 4;

    float4 acc = make_float4(0.f, 0.f, 0.f, 0.f);
    int r0 = g_rowptr[v], r1 = g_rowptr[v + 1];
    for (int e = r0; e < r1; e++) {
        int s = g_csr_src[e];
        float nm = g_csr_norm[e];
        float4 p = *(const float4*)&g_P[(size_t)(base + s) * 1024 + 512 + j];
        acc.x += nm * p.x; acc.y += nm * p.y; acc.z += nm * p.z; acc.w += nm * p.w;
    }
    float dv = g_dinv[v];
    float sn = dv * dv;
    float4 ps = *(const float4*)&g_P[(size_t)n * 1024 + 512 + j];
    acc.x += sn * ps.x; acc.y += sn * ps.y; acc.z += sn * ps.z; acc.w += sn * ps.w;

    float4 own = *(const float4*)&g_P[(size_t)n * 1024 + j];
    float b0 = b20[j + 0] + b21[j + 0];
    float b1 = b20[j + 1] + b21[j + 1];
    float b2 = b20[j + 2] + b21[j + 2];
    float b3 = b20[j + 3] + b21[j + 3];

    float4 h;
    h.x = siluf(own.x + acc.x + b0);
    h.y = siluf(own.y + acc.y + b1);
    h.z = siluf(own.z + acc.z + b2);
    h.w = siluf(own.w + acc.w + b3);
    *(float4*)&g_H2[(size_t)n * HID + j] = h;
}

// ---------------- head: out = G@Wh2 + bh2; log_s = tanh(out[:, :2]), b = out[:, 2:] ----------------
// one warp per node; Wh2 transposed into smem [k][j] for conflict-free access
__global__ void head_kernel(const float* __restrict__ Wh2, const float* __restrict__ bh2,
                            float* __restrict__ out) {
    __shared__ float sw[4 * HID];  // sw[k*512 + j] = Wh2[j*4 + k]
    int tid = threadIdx.x;
    for (int i = tid; i < 4 * HID; i += 256) {
        int jrow = i >> 2, k = i & 3;
        sw[k * HID + jrow] = Wh2[i];
    }
    __syncthreads();

    int warp = tid >> 5, lane = tid & 31;
    int n = blockIdx.x * 8 + warp;
    const float* g = &g_H1[(size_t)n * HID];  // G lives in g_H1 (reused)

    float o0 = 0.f, o1 = 0.f, o2 = 0.f, o3 = 0.f;
#pragma unroll 4
    for (int j = lane; j < HID; j += 32) {
        float gg = g[j];
        o0 += gg * sw[j];
        o1 += gg * sw[HID + j];
        o2 += gg * sw[2 * HID + j];
        o3 += gg * sw[3 * HID + j];
    }
#pragma unroll
    for (int off = 16; off; off >>= 1) {
        o0 += __shfl_down_sync(0xffffffffu, o0, off);
        o1 += __shfl_down_sync(0xffffffffu, o1, off);
        o2 += __shfl_down_sync(0xffffffffu, o2, off);
        o3 += __shfl_down_sync(0xffffffffu, o3, off);
    }
    if (lane == 0) {
        out[2 * n + 0] = tanhf(o0 + bh2[0]);
        out[2 * n + 1] = tanhf(o1 + bh2[1]);
        out[2 * NTOT + 2 * n + 0] = o2 + bh2[2];
        out[2 * NTOT + 2 * n + 1] = o3 + bh2[3];
    }
}

// ---------------- host ----------------
extern "C" void kernel_launch(void* const* d_in, const int* in_sizes, int n_in,
                              void* d_out, int out_size) {
    const float* X   = (const float*)d_in[0];
    const int*   EI  = (const int*)d_in[1];
    const float* W10 = (const float*)d_in[2];
    const float* b10 = (const float*)d_in[3];
    const float* W11 = (const float*)d_in[4];
    const float* b11 = (const float*)d_in[5];
    const float* W20 = (const float*)d_in[6];
    const float* b20 = (const float*)d_in[7];
    const float* W21 = (const float*)d_in[8];
    const float* b21 = (const float*)d_in[9];
    const float* Wh1 = (const float*)d_in[10];
    const float* bh1 = (const float*)d_in[11];
    const float* Wh2 = (const float*)d_in[12];
    const float* bh2 = (const float*)d_in[13];
    float* out = (float*)d_out;

    float *pH1, *pP, *pH2;
    cudaGetSymbolAddress((void**)&pH1, g_H1);
    cudaGetSymbolAddress((void**)&pP,  g_P);
    cudaGetSymbolAddress((void**)&pH2, g_H2);

    zero_cnt_kernel<<<NNB / 256, 256>>>();
    hist_kernel<<<EDG / 256, 256>>>(EI);
    scan_kernel<<<1, 1024>>>();
    scatter_kernel<<<EDG / 256, 256>>>(EI);

    layer1_kernel<<<NTOT / 8, 256>>>(X, W10, b10, W11, b11);

    dim3 g1(512 / 128, NTOT / 128);
    sgemm_kernel<0><<<g1, 256>>>(pH1, W20, pP,       nullptr, NTOT, 512, 512, 512, 512, 1024);
    sgemm_kernel<0><<<g1, 256>>>(pH1, W21, pP + 512, nullptr, NTOT, 512, 512, 512, 512, 1024);

    agg2_kernel<<<NTOT, 128>>>(b20, b21);

    sgemm_kernel<1><<<g1, 256>>>(pH2, Wh1, pH1, bh1, NTOT, 512, 512, 512, 512, 512);

    head_kernel<<<NTOT / 8, 256>>>(Wh2, bh2, out);
}

// round 3
// speedup vs baseline: 2.2374x; 2.2374x over previous
#include <cuda_runtime.h>
#include <cuda_bf16.h>
#include <math.h>
#include <stdint.h>

#define NBATCH 8
#define NNB    4096
#define NTOT   32768
#define EDG    65536
#define HID    512

// ---------------- scratch (device globals; no allocs allowed) ----------------
__device__ float g_H1[(size_t)NTOT * HID];      // 64 MB  (also holds G = silu(H2@Wh1+bh1))
__device__ float g_P [(size_t)NTOT * 1024];     // 128 MB (cols 0:512 = H1@W2_0, 512:1024 = H1@W2_1)
__device__ float g_H2[(size_t)NTOT * HID];      // 64 MB
__device__ __nv_bfloat16 g_Ahi[(size_t)NTOT * HID];  // 32 MB split activations
__device__ __nv_bfloat16 g_Alo[(size_t)NTOT * HID];  // 32 MB
__device__ __nv_bfloat16 g_Whi[3][HID * HID];        // transposed weights [n][k], hi part
__device__ __nv_bfloat16 g_Wlo[3][HID * HID];        // lo part
__device__ int   g_cnt[NNB];
__device__ int   g_rowptr[NNB + 1];
__device__ int   g_csr_src[EDG];
__device__ float g_csr_norm[EDG];
__device__ float g_dinv[NNB];

__device__ __forceinline__ float siluf(float x) {
    return x / (1.0f + expf(-x));
}

// ---------------- PTX helpers (baseline sm_100: mma.sync / ldmatrix / cp.async) ----------------
__device__ __forceinline__ uint32_t smem_u32(const void* p) {
    uint32_t a;
    asm("{ .reg .u64 t; cvta.to.shared.u64 t, %1; cvt.u32.u64 %0, t; }" : "=r"(a) : "l"(p));
    return a;
}

__device__ __forceinline__ void cp16(uint32_t dst, const void* src) {
    asm volatile("cp.async.cg.shared.global [%0], [%1], 16;" :: "r"(dst), "l"(src));
}
#define CP_COMMIT() asm volatile("cp.async.commit_group;" ::: "memory")
#define CP_WAIT(n)  asm volatile("cp.async.wait_group %0;" :: "n"(n) : "memory")

__device__ __forceinline__ void ldsm4(uint32_t* r, uint32_t addr) {
    asm volatile("ldmatrix.sync.aligned.m8n8.x4.shared.b16 {%0,%1,%2,%3}, [%4];"
                 : "=r"(r[0]), "=r"(r[1]), "=r"(r[2]), "=r"(r[3]) : "r"(addr));
}

__device__ __forceinline__ void mma16816(float* c, const uint32_t* a, uint32_t b0, uint32_t b1) {
    asm volatile(
        "mma.sync.aligned.m16n8k16.row.col.f32.bf16.bf16.f32 "
        "{%0,%1,%2,%3}, {%4,%5,%6,%7}, {%8,%9}, {%0,%1,%2,%3};"
        : "+f"(c[0]), "+f"(c[1]), "+f"(c[2]), "+f"(c[3])
        : "r"(a[0]), "r"(a[1]), "r"(a[2]), "r"(a[3]), "r"(b0), "r"(b1));
}

// ---------------- CSR build ----------------
__global__ void zero_cnt_kernel() {
    int i = blockIdx.x * blockDim.x + threadIdx.x;
    if (i < NNB) g_cnt[i] = 0;
}

__global__ void hist_kernel(const int* __restrict__ ei) {
    int e = blockIdx.x * blockDim.x + threadIdx.x;
    if (e < EDG) atomicAdd(&g_cnt[ei[EDG + e]], 1);
}

__global__ void scan_kernel() {
    __shared__ int s[1024];
    int tid = threadIdx.x;
    int c0 = g_cnt[tid * 4 + 0];
    int c1 = g_cnt[tid * 4 + 1];
    int c2 = g_cnt[tid * 4 + 2];
    int c3 = g_cnt[tid * 4 + 3];
    int local = c0 + c1 + c2 + c3;
    s[tid] = local;
    __syncthreads();
    for (int off = 1; off < 1024; off <<= 1) {
        int t = (tid >= off) ? s[tid - off] : 0;
        __syncthreads();
        s[tid] += t;
        __syncthreads();
    }
    int incl = s[tid];
    int excl = incl - local;
    g_rowptr[tid * 4 + 0] = excl;
    g_rowptr[tid * 4 + 1] = excl + c0;
    g_rowptr[tid * 4 + 2] = excl + c0 + c1;
    g_rowptr[tid * 4 + 3] = excl + c0 + c1 + c2;
    if (tid == 1023) g_rowptr[NNB] = incl;
    g_dinv[tid * 4 + 0] = rsqrtf((float)(c0 + 1));
    g_dinv[tid * 4 + 1] = rsqrtf((float)(c1 + 1));
    g_dinv[tid * 4 + 2] = rsqrtf((float)(c2 + 1));
    g_dinv[tid * 4 + 3] = rsqrtf((float)(c3 + 1));
    g_cnt[tid * 4 + 0] = 0;
    g_cnt[tid * 4 + 1] = 0;
    g_cnt[tid * 4 + 2] = 0;
    g_cnt[tid * 4 + 3] = 0;
}

__global__ void scatter_kernel(const int* __restrict__ ei) {
    int e = blockIdx.x * blockDim.x + threadIdx.x;
    if (e >= EDG) return;
    int s = ei[e];
    int d = ei[EDG + e];
    int pos = g_rowptr[d] + atomicAdd(&g_cnt[d], 1);
    g_csr_src[pos]  = s;
    g_csr_norm[pos] = g_dinv[s] * g_dinv[d];
}

// ---------------- layer 1 ----------------
__global__ void layer1_kernel(const float* __restrict__ X,
                              const float* __restrict__ W10, const float* __restrict__ b10,
                              const float* __restrict__ W11, const float* __restrict__ b11) {
    __shared__ float sW[5 * HID];
    int tid = threadIdx.x;
    for (int i = tid; i < HID; i += 256) {
        sW[i]           = W10[i];
        sW[HID + i]     = W10[HID + i];
        sW[2 * HID + i] = W11[i];
        sW[3 * HID + i] = W11[HID + i];
        sW[4 * HID + i] = b10[i] + b11[i];
    }
    __syncthreads();

    int warp = tid >> 5, lane = tid & 31;
    int n = blockIdx.x * 8 + warp;
    int v = n & (NNB - 1);
    int base = n & ~(NNB - 1);

    float x0 = X[2 * n], x1 = X[2 * n + 1];
    float a0 = 0.f, a1 = 0.f;
    int r0 = g_rowptr[v], r1 = g_rowptr[v + 1];
    for (int e = r0 + lane; e < r1; e += 32) {
        int s = g_csr_src[e];
        float nm = g_csr_norm[e];
        a0 += nm * X[2 * (base + s)];
        a1 += nm * X[2 * (base + s) + 1];
    }
#pragma unroll
    for (int off = 16; off; off >>= 1) {
        a0 += __shfl_down_sync(0xffffffffu, a0, off);
        a1 += __shfl_down_sync(0xffffffffu, a1, off);
    }
    a0 = __shfl_sync(0xffffffffu, a0, 0);
    a1 = __shfl_sync(0xffffffffu, a1, 0);
    float dv = g_dinv[v];
    float sn = dv * dv;
    a0 += sn * x0;
    a1 += sn * x1;

    float* out = &g_H1[(size_t)n * HID];
#pragma unroll 4
    for (int j = lane; j < HID; j += 32) {
        float h = x0 * sW[j] + x1 * sW[HID + j] + a0 * sW[2 * HID + j] + a1 * sW[3 * HID + j] + sW[4 * HID + j];
        out[j] = siluf(h);
    }
}

// ---------------- split fp32 activation into (hi, lo) bf16 ----------------
__device__ __forceinline__ uint32_t pk2(__nv_bfloat16 a, __nv_bfloat16 b) {
    return (uint32_t)__bfloat16_as_ushort(a) | ((uint32_t)__bfloat16_as_ushort(b) << 16);
}

__global__ void split_act_kernel(const float* __restrict__ src) {
    size_t i = (size_t)blockIdx.x * blockDim.x + threadIdx.x;  // per float4
    float4 v = ((const float4*)src)[i];
    __nv_bfloat16 h0 = __float2bfloat16(v.x), h1 = __float2bfloat16(v.y);
    __nv_bfloat16 h2 = __float2bfloat16(v.z), h3 = __float2bfloat16(v.w);
    __nv_bfloat16 l0 = __float2bfloat16(v.x - __bfloat162float(h0));
    __nv_bfloat16 l1 = __float2bfloat16(v.y - __bfloat162float(h1));
    __nv_bfloat16 l2 = __float2bfloat16(v.z - __bfloat162float(h2));
    __nv_bfloat16 l3 = __float2bfloat16(v.w - __bfloat162float(h3));
    ((uint2*)g_Ahi)[i] = make_uint2(pk2(h0, h1), pk2(h2, h3));
    ((uint2*)g_Alo)[i] = make_uint2(pk2(l0, l1), pk2(l2, l3));
}

// ---------------- transpose + split weight: W[k][n] -> T[n][k] (hi, lo bf16) ----------------
__global__ void split_w_kernel(const float* __restrict__ W,
                               __nv_bfloat16* __restrict__ Thi, __nv_bfloat16* __restrict__ Tlo) {
    __shared__ float tile[32][33];
    int bn = blockIdx.x * 32, bk = blockIdx.y * 32;
    int tx = threadIdx.x;
    for (int ty = threadIdx.y; ty < 32; ty += 8)
        tile[ty][tx] = W[(size_t)(bk + ty) * HID + bn + tx];
    __syncthreads();
    for (int ty = threadIdx.y; ty < 32; ty += 8) {
        float x = tile[tx][ty];  // = W[bk+tx][bn+ty]
        __nv_bfloat16 h = __float2bfloat16(x);
        __nv_bfloat16 l = __float2bfloat16(x - __bfloat162float(h));
        size_t o = (size_t)(bn + ty) * HID + bk + tx;
        Thi[o] = h;
        Tlo[o] = l;
    }
}

// ---------------- HMMA split-precision GEMM ----------------
// C[M,N] = A[M,K] @ W[K,N]; A as (Ahi,Alo) [M][K] bf16, W as (Bhi,Blo) [N][K] bf16.
// fp32 accumulation of hi*hi + hi*lo + lo*hi via mma.sync.m16n8k16.
// CTA 128x128, 8 warps of 64x32, BK=32, cp.async double buffer.
// smem tile: 128 rows x 80 bytes (40 bf16, 32 used) -> ldmatrix bank-conflict-free.
#define TROW_B   80
#define TILE_B   (128 * TROW_B)          // 10240
#define STAGE_B  (4 * TILE_B)            // 40960: Ahi, Alo, Bhi, Blo
#define GEMM_SMEM (2 * STAGE_B)          // 81920

__device__ __forceinline__ void load_stage(uint32_t sb, uint32_t stg,
                                           const __nv_bfloat16* Ahi, const __nv_bfloat16* Alo,
                                           const __nv_bfloat16* Bhi, const __nv_bfloat16* Blo,
                                           int m0, int n0, int kc, int tid) {
#pragma unroll
    for (int i = 0; i < 2; i++) {
        int idx = tid + i * 256;           // 0..511
        int r = idx >> 2, g = idx & 3;     // row 0..127, 16B chunk 0..3
        uint32_t doff = stg + (uint32_t)(r * TROW_B + g * 16);
        size_t asrc = (size_t)(m0 + r) * HID + kc + g * 8;
        size_t bsrc = (size_t)(n0 + r) * HID + kc + g * 8;
        cp16(sb + doff,                Ahi + asrc);
        cp16(sb + doff + TILE_B,       Alo + asrc);
        cp16(sb + doff + 2 * TILE_B,   Bhi + bsrc);
        cp16(sb + doff + 3 * TILE_B,   Blo + bsrc);
    }
}

template <int MODE>  // 0: plain store, 1: silu(acc + bias[col])
__global__ void __launch_bounds__(256, 2)
hmma_gemm_kernel(const __nv_bfloat16* __restrict__ Ahi, const __nv_bfloat16* __restrict__ Alo,
                 const __nv_bfloat16* __restrict__ Bhi, const __nv_bfloat16* __restrict__ Blo,
                 float* __restrict__ C, const float* __restrict__ bias, int ldc) {
    extern __shared__ __align__(128) char smem[];
    uint32_t sb = smem_u32(smem);
    int tid = threadIdx.x, wid = tid >> 5, lane = tid & 31;
    int n0 = blockIdx.x * 128;
    int m0 = blockIdx.y * 128;
    int wm = (wid & 1) * 64;       // warp m offset within tile
    int wn = (wid >> 1) * 32;      // warp n offset within tile

    float acc[4][4][4];
#pragma unroll
    for (int i = 0; i < 4; i++)
#pragma unroll
        for (int j = 0; j < 4; j++)
#pragma unroll
            for (int q = 0; q < 4; q++) acc[i][j][q] = 0.f;

    // per-lane ldmatrix row offsets
    int lrow = lane & 15;
    uint32_t kByte = (uint32_t)(lane >> 4) * 16;  // k-half select: +8 elems = 16 bytes
    uint32_t aRow[4], bRow[2];
#pragma unroll
    for (int i = 0; i < 4; i++) aRow[i] = (uint32_t)((wm + i * 16 + lrow) * TROW_B) + kByte;
#pragma unroll
    for (int p = 0; p < 2; p++) bRow[p] = (uint32_t)((wn + p * 16 + lrow) * TROW_B) + kByte;

    const int nt = HID / 32;  // 16

    load_stage(sb, 0, Ahi, Alo, Bhi, Blo, m0, n0, 0, tid);
    CP_COMMIT();

    for (int t = 0; t < nt; t++) {
        uint32_t stg = (uint32_t)(t & 1) * STAGE_B;
        if (t + 1 < nt) {
            load_stage(sb, (uint32_t)((t + 1) & 1) * STAGE_B, Ahi, Alo, Bhi, Blo, m0, n0, (t + 1) * 32, tid);
            CP_COMMIT();
            CP_WAIT(1);
        } else {
            CP_WAIT(0);
        }
        __syncthreads();

        uint32_t aHiB = sb + stg, aLoB = aHiB + TILE_B;
        uint32_t bHiB = aHiB + 2 * TILE_B, bLoB = aHiB + 3 * TILE_B;

#pragma unroll
        for (int kk = 0; kk < 2; kk++) {
            uint32_t ko = (uint32_t)kk * 32;  // 16 elems = 32 bytes
            uint32_t ah[4][4], bh[2][4], tf[4][4];
#pragma unroll
            for (int i = 0; i < 4; i++) ldsm4(ah[i], aHiB + aRow[i] + ko);
#pragma unroll
            for (int p = 0; p < 2; p++) ldsm4(bh[p], bHiB + bRow[p] + ko);
            // hi*hi
#pragma unroll
            for (int i = 0; i < 4; i++)
#pragma unroll
                for (int p = 0; p < 2; p++) {
                    mma16816(acc[i][2 * p],     ah[i], bh[p][0], bh[p][2]);
                    mma16816(acc[i][2 * p + 1], ah[i], bh[p][1], bh[p][3]);
                }
            // hi*lo
#pragma unroll
            for (int p = 0; p < 2; p++) ldsm4(tf[p], bLoB + bRow[p] + ko);
#pragma unroll
            for (int i = 0; i < 4; i++)
#pragma unroll
                for (int p = 0; p < 2; p++) {
                    mma16816(acc[i][2 * p],     ah[i], tf[p][0], tf[p][2]);
                    mma16816(acc[i][2 * p + 1], ah[i], tf[p][1], tf[p][3]);
                }
            // lo*hi
#pragma unroll
            for (int i = 0; i < 4; i++) ldsm4(tf[i], aLoB + aRow[i] + ko);
#pragma unroll
            for (int i = 0; i < 4; i++)
#pragma unroll
                for (int p = 0; p < 2; p++) {
                    mma16816(acc[i][2 * p],     tf[i], bh[p][0], bh[p][2]);
                    mma16816(acc[i][2 * p + 1], tf[i], bh[p][1], bh[p][3]);
                }
        }
        __syncthreads();
    }

    // epilogue
    int quad = lane >> 2, tq = lane & 3;
#pragma unroll
    for (int i = 0; i < 4; i++) {
        int row = m0 + wm + i * 16 + quad;
#pragma unroll
        for (int j = 0; j < 4; j++) {
            int col = n0 + wn + j * 8 + tq * 2;
            float2 v0, v1;
            v0.x = acc[i][j][0]; v0.y = acc[i][j][1];
            v1.x = acc[i][j][2]; v1.y = acc[i][j][3];
            if (MODE == 1) {
                float bb0 = bias[col], bb1 = bias[col + 1];
                v0.x = siluf(v0.x + bb0); v0.y = siluf(v0.y + bb1);
                v1.x = siluf(v1.x + bb0); v1.y = siluf(v1.y + bb1);
            }
            *(float2*)(C + (size_t)row * ldc + col)       = v0;
            *(float2*)(C + (size_t)(row + 8) * ldc + col) = v1;
        }
    }
}

// ---------------- layer 2 combine ----------------
__global__ void agg2_kernel(const float* __restrict__ b20, const float* __restrict__ b21) {
    int n = blockIdx.x;
    int tid = threadIdx.x;
    int v = n & (NNB - 1);
    int base = n & ~(NNB - 1);
    int j = tid * 4;

    float4 acc = make_float4(0.f, 0.f, 0.f, 0.f);
    int r0 = g_rowptr[v], r1 = g_rowptr[v + 1];
    for (int e = r0; e < r1; e++) {
        int s = g_csr_src[e];
        float nm = g_csr_norm[e];
        float4 p = *(const float4*)&g_P[(size_t)(base + s) * 1024 + 512 + j];
        acc.x += nm * p.x; acc.y += nm * p.y; acc.z += nm * p.z; acc.w += nm * p.w;
    }
    float dv = g_dinv[v];
    float sn = dv * dv;
    float4 ps = *(const float4*)&g_P[(size_t)n * 1024 + 512 + j];
    acc.x += sn * ps.x; acc.y += sn * ps.y; acc.z += sn * ps.z; acc.w += sn * ps.w;

    float4 own = *(const float4*)&g_P[(size_t)n * 1024 + j];
    float b0 = b20[j + 0] + b21[j + 0];
    float b1 = b20[j + 1] + b21[j + 1];
    float b2 = b20[j + 2] + b21[j + 2];
    float b3 = b20[j + 3] + b21[j + 3];

    float4 h;
    h.x = siluf(own.x + acc.x + b0);
    h.y = siluf(own.y + acc.y + b1);
    h.z = siluf(own.z + acc.z + b2);
    h.w = siluf(own.w + acc.w + b3);
    *(float4*)&g_H2[(size_t)n * HID + j] = h;
}

// ---------------- head ----------------
__global__ void head_kernel(const float* __restrict__ Wh2, const float* __restrict__ bh2,
                            float* __restrict__ out) {
    __shared__ float sw[4 * HID];
    int tid = threadIdx.x;
    for (int i = tid; i < 4 * HID; i += 256) {
        int jrow = i >> 2, k = i & 3;
        sw[k * HID + jrow] = Wh2[i];
    }
    __syncthreads();

    int warp = tid >> 5, lane = tid & 31;
    int n = blockIdx.x * 8 + warp;
    const float* g = &g_H1[(size_t)n * HID];

    float o0 = 0.f, o1 = 0.f, o2 = 0.f, o3 = 0.f;
#pragma unroll 4
    for (int j = lane; j < HID; j += 32) {
        float gg = g[j];
        o0 += gg * sw[j];
        o1 += gg * sw[HID + j];
        o2 += gg * sw[2 * HID + j];
        o3 += gg * sw[3 * HID + j];
    }
#pragma unroll
    for (int off = 16; off; off >>= 1) {
        o0 += __shfl_down_sync(0xffffffffu, o0, off);
        o1 += __shfl_down_sync(0xffffffffu, o1, off);
        o2 += __shfl_down_sync(0xffffffffu, o2, off);
        o3 += __shfl_down_sync(0xffffffffu, o3, off);
    }
    if (lane == 0) {
        out[2 * n + 0] = tanhf(o0 + bh2[0]);
        out[2 * n + 1] = tanhf(o1 + bh2[1]);
        out[2 * NTOT + 2 * n + 0] = o2 + bh2[2];
        out[2 * NTOT + 2 * n + 1] = o3 + bh2[3];
    }
}

// ---------------- host ----------------
extern "C" void kernel_launch(void* const* d_in, const int* in_sizes, int n_in,
                              void* d_out, int out_size) {
    const float* X   = (const float*)d_in[0];
    const int*   EI  = (const int*)d_in[1];
    const float* W10 = (const float*)d_in[2];
    const float* b10 = (const float*)d_in[3];
    const float* W11 = (const float*)d_in[4];
    const float* b11 = (const float*)d_in[5];
    const float* W20 = (const float*)d_in[6];
    const float* b20 = (const float*)d_in[7];
    const float* W21 = (const float*)d_in[8];
    const float* b21 = (const float*)d_in[9];
    const float* Wh1 = (const float*)d_in[10];
    const float* bh1 = (const float*)d_in[11];
    const float* Wh2 = (const float*)d_in[12];
    const float* bh2 = (const float*)d_in[13];
    float* out = (float*)d_out;

    float *pH1, *pP, *pH2;
    __nv_bfloat16 *pAhi, *pAlo, *pWhi, *pWlo;
    cudaGetSymbolAddress((void**)&pH1, g_H1);
    cudaGetSymbolAddress((void**)&pP,  g_P);
    cudaGetSymbolAddress((void**)&pH2, g_H2);
    cudaGetSymbolAddress((void**)&pAhi, g_Ahi);
    cudaGetSymbolAddress((void**)&pAlo, g_Alo);
    cudaGetSymbolAddress((void**)&pWhi, g_Whi);
    cudaGetSymbolAddress((void**)&pWlo, g_Wlo);

    cudaFuncSetAttribute(hmma_gemm_kernel<0>, cudaFuncAttributeMaxDynamicSharedMemorySize, GEMM_SMEM);
    cudaFuncSetAttribute(hmma_gemm_kernel<1>, cudaFuncAttributeMaxDynamicSharedMemorySize, GEMM_SMEM);

    // graph norm + CSR
    zero_cnt_kernel<<<NNB / 256, 256>>>();
    hist_kernel<<<EDG / 256, 256>>>(EI);
    scan_kernel<<<1, 1024>>>();
    scatter_kernel<<<EDG / 256, 256>>>(EI);

    // weight preprocessing (transpose + bf16 split)
    dim3 wb(32, 8), wg(16, 16);
    split_w_kernel<<<wg, wb>>>(W20, pWhi + 0 * HID * HID, pWlo + 0 * HID * HID);
    split_w_kernel<<<wg, wb>>>(W21, pWhi + 1 * HID * HID, pWlo + 1 * HID * HID);
    split_w_kernel<<<wg, wb>>>(Wh1, pWhi + 2 * HID * HID, pWlo + 2 * HID * HID);

    // layer 1
    layer1_kernel<<<NTOT / 8, 256>>>(X, W10, b10, W11, b11);

    // layer 2 GEMMs (tensor cores via mma.sync)
    split_act_kernel<<<(NTOT * HID / 4) / 256, 256>>>(pH1);
    dim3 gg(4, NTOT / 128);
    hmma_gemm_kernel<0><<<gg, 256, GEMM_SMEM>>>(pAhi, pAlo, pWhi + 0 * HID * HID, pWlo + 0 * HID * HID,
                                                pP, nullptr, 1024);
    hmma_gemm_kernel<0><<<gg, 256, GEMM_SMEM>>>(pAhi, pAlo, pWhi + 1 * HID * HID, pWlo + 1 * HID * HID,
                                                pP + 512, nullptr, 1024);
    agg2_kernel<<<NTOT, 128>>>(b20, b21);

    // head pre-GEMM with fused bias+silu
    split_act_kernel<<<(NTOT * HID / 4) / 256, 256>>>(pH2);
    hmma_gemm_kernel<1><<<gg, 256, GEMM_SMEM>>>(pAhi, pAlo, pWhi + 2 * HID * HID, pWlo + 2 * HID * HID,
                                                pH1, bh1, 512);

    head_kernel<<<NTOT / 8, 256>>>(Wh2, bh2, out);
}

// round 4
// speedup vs baseline: 2.3616x; 1.0555x over previous
#include <cuda_runtime.h>
#include <cuda_bf16.h>
#include <math.h>
#include <stdint.h>

#define NBATCH 8
#define NNB    4096
#define NTOT   32768
#define EDG    65536
#define HID    512

// ---------------- scratch (device globals; no allocs allowed) ----------------
// A matrix for layer-2 GEMM: [M][1024] split bf16; cols 0:512 = H1, 512:1024 = agg(H1)
__device__ __nv_bfloat16 g_Ahi[(size_t)NTOT * 1024];   // 64 MB
__device__ __nv_bfloat16 g_Alo[(size_t)NTOT * 1024];   // 64 MB
// A matrix for head GEMM: [M][512] split bf16 (= H2)
__device__ __nv_bfloat16 g_Bhi[(size_t)NTOT * HID];    // 32 MB
__device__ __nv_bfloat16 g_Blo[(size_t)NTOT * HID];    // 32 MB
__device__ float g_G[(size_t)NTOT * HID];              // 64 MB (G = silu(H2@Wh1+bh1))
// weights transposed [n][k], split
__device__ __nv_bfloat16 g_W2hi[HID * 1024];           // stacked [W2_0; W2_1]
__device__ __nv_bfloat16 g_W2lo[HID * 1024];
__device__ __nv_bfloat16 g_Whhi[HID * HID];            // Wh1
__device__ __nv_bfloat16 g_Whlo[HID * HID];
__device__ int   g_cnt[NNB];
__device__ int   g_rowptr[NNB + 1];
__device__ int   g_csr_src[EDG];
__device__ float g_csr_norm[EDG];
__device__ float g_dinv[NNB];

__device__ __forceinline__ float siluf(float x) {
    return x / (1.0f + expf(-x));
}

__device__ __forceinline__ uint32_t pk2(__nv_bfloat16 a, __nv_bfloat16 b) {
    return (uint32_t)__bfloat16_as_ushort(a) | ((uint32_t)__bfloat16_as_ushort(b) << 16);
}
__device__ __forceinline__ void unpk2(uint32_t u, float& a, float& b) {
    a = __bfloat162float(__ushort_as_bfloat16((unsigned short)(u & 0xffff)));
    b = __bfloat162float(__ushort_as_bfloat16((unsigned short)(u >> 16)));
}
__device__ __forceinline__ void split1(float v, __nv_bfloat16& h, __nv_bfloat16& l) {
    h = __float2bfloat16(v);
    l = __float2bfloat16(v - __bfloat162float(h));
}

// ---------------- PTX helpers (baseline sm_100: mma.sync / ldmatrix / cp.async) ----------------
__device__ __forceinline__ uint32_t smem_u32(const void* p) {
    uint32_t a;
    asm("{ .reg .u64 t; cvta.to.shared.u64 t, %1; cvt.u32.u64 %0, t; }" : "=r"(a) : "l"(p));
    return a;
}

__device__ __forceinline__ void cp16(uint32_t dst, const void* src) {
    asm volatile("cp.async.cg.shared.global [%0], [%1], 16;" :: "r"(dst), "l"(src));
}
#define CP_COMMIT() asm volatile("cp.async.commit_group;" ::: "memory")
#define CP_WAIT(n)  asm volatile("cp.async.wait_group %0;" :: "n"(n) : "memory")

__device__ __forceinline__ void ldsm4(uint32_t* r, uint32_t addr) {
    asm volatile("ldmatrix.sync.aligned.m8n8.x4.shared.b16 {%0,%1,%2,%3}, [%4];"
                 : "=r"(r[0]), "=r"(r[1]), "=r"(r[2]), "=r"(r[3]) : "r"(addr));
}

__device__ __forceinline__ void mma16816(float* c, const uint32_t* a, uint32_t b0, uint32_t b1) {
    asm volatile(
        "mma.sync.aligned.m16n8k16.row.col.f32.bf16.bf16.f32 "
        "{%0,%1,%2,%3}, {%4,%5,%6,%7}, {%8,%9}, {%0,%1,%2,%3};"
        : "+f"(c[0]), "+f"(c[1]), "+f"(c[2]), "+f"(c[3])
        : "r"(a[0]), "r"(a[1]), "r"(a[2]), "r"(a[3]), "r"(b0), "r"(b1));
}

// ---------------- CSR build ----------------
__global__ void zero_cnt_kernel() {
    int i = blockIdx.x * blockDim.x + threadIdx.x;
    if (i < NNB) g_cnt[i] = 0;
}

__global__ void hist_kernel(const int* __restrict__ ei) {
    int e = blockIdx.x * blockDim.x + threadIdx.x;
    if (e < EDG) atomicAdd(&g_cnt[ei[EDG + e]], 1);
}

__global__ void scan_kernel() {
    __shared__ int s[1024];
    int tid = threadIdx.x;
    int c0 = g_cnt[tid * 4 + 0];
    int c1 = g_cnt[tid * 4 + 1];
    int c2 = g_cnt[tid * 4 + 2];
    int c3 = g_cnt[tid * 4 + 3];
    int local = c0 + c1 + c2 + c3;
    s[tid] = local;
    __syncthreads();
    for (int off = 1; off < 1024; off <<= 1) {
        int t = (tid >= off) ? s[tid - off] : 0;
        __syncthreads();
        s[tid] += t;
        __syncthreads();
    }
    int incl = s[tid];
    int excl = incl - local;
    g_rowptr[tid * 4 + 0] = excl;
    g_rowptr[tid * 4 + 1] = excl + c0;
    g_rowptr[tid * 4 + 2] = excl + c0 + c1;
    g_rowptr[tid * 4 + 3] = excl + c0 + c1 + c2;
    if (tid == 1023) g_rowptr[NNB] = incl;
    g_dinv[tid * 4 + 0] = rsqrtf((float)(c0 + 1));
    g_dinv[tid * 4 + 1] = rsqrtf((float)(c1 + 1));
    g_dinv[tid * 4 + 2] = rsqrtf((float)(c2 + 1));
    g_dinv[tid * 4 + 3] = rsqrtf((float)(c3 + 1));
    g_cnt[tid * 4 + 0] = 0;
    g_cnt[tid * 4 + 1] = 0;
    g_cnt[tid * 4 + 2] = 0;
    g_cnt[tid * 4 + 3] = 0;
}

__global__ void scatter_kernel(const int* __restrict__ ei) {
    int e = blockIdx.x * blockDim.x + threadIdx.x;
    if (e >= EDG) return;
    int s = ei[e];
    int d = ei[EDG + e];
    int pos = g_rowptr[d] + atomicAdd(&g_cnt[d], 1);
    g_csr_src[pos]  = s;
    g_csr_norm[pos] = g_dinv[s] * g_dinv[d];
}

// ---------------- layer 1: writes split bf16 H1 into g_Ahi/g_Alo cols 0:512 (stride 1024) ----------------
__global__ void layer1_kernel(const float* __restrict__ X,
                              const float* __restrict__ W10, const float* __restrict__ b10,
                              const float* __restrict__ W11, const float* __restrict__ b11) {
    __shared__ float sW[5 * HID];
    int tid = threadIdx.x;
    for (int i = tid; i < HID; i += 256) {
        sW[i]           = W10[i];
        sW[HID + i]     = W10[HID + i];
        sW[2 * HID + i] = W11[i];
        sW[3 * HID + i] = W11[HID + i];
        sW[4 * HID + i] = b10[i] + b11[i];
    }
    __syncthreads();

    int warp = tid >> 5, lane = tid & 31;
    int n = blockIdx.x * 8 + warp;
    int v = n & (NNB - 1);
    int base = n & ~(NNB - 1);

    float x0 = X[2 * n], x1 = X[2 * n + 1];
    float a0 = 0.f, a1 = 0.f;
    int r0 = g_rowptr[v], r1 = g_rowptr[v + 1];
    for (int e = r0 + lane; e < r1; e += 32) {
        int s = g_csr_src[e];
        float nm = g_csr_norm[e];
        a0 += nm * X[2 * (base + s)];
        a1 += nm * X[2 * (base + s) + 1];
    }
#pragma unroll
    for (int off = 16; off; off >>= 1) {
        a0 += __shfl_down_sync(0xffffffffu, a0, off);
        a1 += __shfl_down_sync(0xffffffffu, a1, off);
    }
    a0 = __shfl_sync(0xffffffffu, a0, 0);
    a1 = __shfl_sync(0xffffffffu, a1, 0);
    float dv = g_dinv[v];
    float sn = dv * dv;
    a0 += sn * x0;
    a1 += sn * x1;

    __nv_bfloat16* oh = &g_Ahi[(size_t)n * 1024];
    __nv_bfloat16* ol = &g_Alo[(size_t)n * 1024];
#pragma unroll 4
    for (int j = lane; j < HID; j += 32) {
        float h = x0 * sW[j] + x1 * sW[HID + j] + a0 * sW[2 * HID + j] + a1 * sW[3 * HID + j] + sW[4 * HID + j];
        float sv = siluf(h);
        __nv_bfloat16 hh, ll;
        split1(sv, hh, ll);
        oh[j] = hh;
        ol[j] = ll;
    }
}

// ---------------- aggregate H1 -> g_Ahi/g_Alo cols 512:1024 ----------------
// one block (128 threads) per node; thread handles 4 consecutive features
__global__ void aggH_kernel() {
    int n = blockIdx.x;
    int tid = threadIdx.x;
    int v = n & (NNB - 1);
    int base = n & ~(NNB - 1);
    int j = tid * 4;

    float acc0 = 0.f, acc1 = 0.f, acc2 = 0.f, acc3 = 0.f;
    int r0 = g_rowptr[v], r1 = g_rowptr[v + 1];
    for (int e = r0; e < r1; e++) {
        int s = g_csr_src[e];
        float nm = g_csr_norm[e];
        size_t ro = (size_t)(base + s) * 1024 + j;
        uint2 uh = *(const uint2*)&g_Ahi[ro];
        uint2 ul = *(const uint2*)&g_Alo[ro];
        float h0, h1, h2, h3, l0, l1, l2, l3;
        unpk2(uh.x, h0, h1); unpk2(uh.y, h2, h3);
        unpk2(ul.x, l0, l1); unpk2(ul.y, l2, l3);
        acc0 += nm * (h0 + l0);
        acc1 += nm * (h1 + l1);
        acc2 += nm * (h2 + l2);
        acc3 += nm * (h3 + l3);
    }
    // self loop
    {
        float dv = g_dinv[v];
        float sn = dv * dv;
        size_t ro = (size_t)n * 1024 + j;
        uint2 uh = *(const uint2*)&g_Ahi[ro];
        uint2 ul = *(const uint2*)&g_Alo[ro];
        float h0, h1, h2, h3, l0, l1, l2, l3;
        unpk2(uh.x, h0, h1); unpk2(uh.y, h2, h3);
        unpk2(ul.x, l0, l1); unpk2(ul.y, l2, l3);
        acc0 += sn * (h0 + l0);
        acc1 += sn * (h1 + l1);
        acc2 += sn * (h2 + l2);
        acc3 += sn * (h3 + l3);
    }
    __nv_bfloat16 h0, h1, h2, h3, l0, l1, l2, l3;
    split1(acc0, h0, l0); split1(acc1, h1, l1);
    split1(acc2, h2, l2); split1(acc3, h3, l3);
    size_t wo = (size_t)n * 1024 + 512 + j;
    *(uint2*)&g_Ahi[wo] = make_uint2(pk2(h0, h1), pk2(h2, h3));
    *(uint2*)&g_Alo[wo] = make_uint2(pk2(l0, l1), pk2(l2, l3));
}

// ---------------- transpose + split weight: W[k][n] (HIDxHID) -> T[n][koff+k], stride ldT ----------------
__global__ void split_w_kernel(const float* __restrict__ W,
                               __nv_bfloat16* __restrict__ Thi, __nv_bfloat16* __restrict__ Tlo,
                               int ldT, int koff) {
    __shared__ float tile[32][33];
    int bn = blockIdx.x * 32, bk = blockIdx.y * 32;
    int tx = threadIdx.x;
    for (int ty = threadIdx.y; ty < 32; ty += 8)
        tile[ty][tx] = W[(size_t)(bk + ty) * HID + bn + tx];
    __syncthreads();
    for (int ty = threadIdx.y; ty < 32; ty += 8) {
        float x = tile[tx][ty];  // = W[bk+tx][bn+ty]
        __nv_bfloat16 h, l;
        split1(x, h, l);
        size_t o = (size_t)(bn + ty) * ldT + koff + bk + tx;
        Thi[o] = h;
        Tlo[o] = l;
    }
}

// ---------------- HMMA split-precision GEMM ----------------
// C[M,N] = A[M,K] @ W[K,N]; A as (Ahi,Alo) [M][lda] bf16, W transposed as (Bhi,Blo) [N][ldb] bf16.
// fp32 accumulation of hi*hi + hi*lo + lo*hi via mma.sync.m16n8k16.
// CTA 128x128, 8 warps of 64x32, BK=32, cp.async double buffer.
// MODE 1: Cf = silu(acc + bias1[col]), fp32
// MODE 2: (Chi,Clo) = split(silu(acc + bias1[col] + bias2[col]))
#define TROW_B   80
#define TILE_B   (128 * TROW_B)          // 10240
#define STAGE_B  (4 * TILE_B)            // 40960
#define GEMM_SMEM (2 * STAGE_B)          // 81920

__device__ __forceinline__ void load_stage(uint32_t sb, uint32_t stg,
                                           const __nv_bfloat16* Ahi, const __nv_bfloat16* Alo,
                                           const __nv_bfloat16* Bhi, const __nv_bfloat16* Blo,
                                           int m0, int n0, int kc, int lda, int ldb, int tid) {
#pragma unroll
    for (int i = 0; i < 2; i++) {
        int idx = tid + i * 256;           // 0..511
        int r = idx >> 2, g = idx & 3;     // row 0..127, 16B chunk 0..3
        uint32_t doff = stg + (uint32_t)(r * TROW_B + g * 16);
        size_t asrc = (size_t)(m0 + r) * lda + kc + g * 8;
        size_t bsrc = (size_t)(n0 + r) * ldb + kc + g * 8;
        cp16(sb + doff,                Ahi + asrc);
        cp16(sb + doff + TILE_B,       Alo + asrc);
        cp16(sb + doff + 2 * TILE_B,   Bhi + bsrc);
        cp16(sb + doff + 3 * TILE_B,   Blo + bsrc);
    }
}

template <int MODE>
__global__ void __launch_bounds__(256, 2)
hmma_gemm_kernel(const __nv_bfloat16* __restrict__ Ahi, const __nv_bfloat16* __restrict__ Alo,
                 const __nv_bfloat16* __restrict__ Bhi, const __nv_bfloat16* __restrict__ Blo,
                 float* __restrict__ Cf,
                 __nv_bfloat16* __restrict__ Chi, __nv_bfloat16* __restrict__ Clo,
                 const float* __restrict__ bias1, const float* __restrict__ bias2,
                 int lda, int ldb, int ldc, int K) {
    extern __shared__ __align__(128) char smem[];
    uint32_t sb = smem_u32(smem);
    int tid = threadIdx.x, wid = tid >> 5, lane = tid & 31;
    int n0 = blockIdx.x * 128;
    int m0 = blockIdx.y * 128;
    int wm = (wid & 1) * 64;
    int wn = (wid >> 1) * 32;

    float acc[4][4][4];
#pragma unroll
    for (int i = 0; i < 4; i++)
#pragma unroll
        for (int j = 0; j < 4; j++)
#pragma unroll
            for (int q = 0; q < 4; q++) acc[i][j][q] = 0.f;

    int lrow = lane & 15;
    uint32_t kByte = (uint32_t)(lane >> 4) * 16;
    uint32_t aRow[4], bRow[2];
#pragma unroll
    for (int i = 0; i < 4; i++) aRow[i] = (uint32_t)((wm + i * 16 + lrow) * TROW_B) + kByte;
#pragma unroll
    for (int p = 0; p < 2; p++) bRow[p] = (uint32_t)((wn + p * 16 + lrow) * TROW_B) + kByte;

    const int nt = K / 32;

    load_stage(sb, 0, Ahi, Alo, Bhi, Blo, m0, n0, 0, lda, ldb, tid);
    CP_COMMIT();

    for (int t = 0; t < nt; t++) {
        uint32_t stg = (uint32_t)(t & 1) * STAGE_B;
        if (t + 1 < nt) {
            load_stage(sb, (uint32_t)((t + 1) & 1) * STAGE_B, Ahi, Alo, Bhi, Blo, m0, n0,
                       (t + 1) * 32, lda, ldb, tid);
            CP_COMMIT();
            CP_WAIT(1);
        } else {
            CP_WAIT(0);
        }
        __syncthreads();

        uint32_t aHiB = sb + stg, aLoB = aHiB + TILE_B;
        uint32_t bHiB = aHiB + 2 * TILE_B, bLoB = aHiB + 3 * TILE_B;

#pragma unroll
        for (int kk = 0; kk < 2; kk++) {
            uint32_t ko = (uint32_t)kk * 32;
            uint32_t ah[4][4], bh[2][4], tf[4][4];
#pragma unroll
            for (int i = 0; i < 4; i++) ldsm4(ah[i], aHiB + aRow[i] + ko);
#pragma unroll
            for (int p = 0; p < 2; p++) ldsm4(bh[p], bHiB + bRow[p] + ko);
            // hi*hi
#pragma unroll
            for (int i = 0; i < 4; i++)
#pragma unroll
                for (int p = 0; p < 2; p++) {
                    mma16816(acc[i][2 * p],     ah[i], bh[p][0], bh[p][2]);
                    mma16816(acc[i][2 * p + 1], ah[i], bh[p][1], bh[p][3]);
                }
            // hi*lo
#pragma unroll
            for (int p = 0; p < 2; p++) ldsm4(tf[p], bLoB + bRow[p] + ko);
#pragma unroll
            for (int i = 0; i < 4; i++)
#pragma unroll
                for (int p = 0; p < 2; p++) {
                    mma16816(acc[i][2 * p],     ah[i], tf[p][0], tf[p][2]);
                    mma16816(acc[i][2 * p + 1], ah[i], tf[p][1], tf[p][3]);
                }
            // lo*hi
#pragma unroll
            for (int i = 0; i < 4; i++) ldsm4(tf[i], aLoB + aRow[i] + ko);
#pragma unroll
            for (int i = 0; i < 4; i++)
#pragma unroll
                for (int p = 0; p < 2; p++) {
                    mma16816(acc[i][2 * p],     tf[i], bh[p][0], bh[p][2]);
                    mma16816(acc[i][2 * p + 1], tf[i], bh[p][1], bh[p][3]);
                }
        }
        __syncthreads();
    }

    // epilogue
    int quad = lane >> 2, tq = lane & 3;
#pragma unroll
    for (int i = 0; i < 4; i++) {
        int row = m0 + wm + i * 16 + quad;
#pragma unroll
        for (int j = 0; j < 4; j++) {
            int col = n0 + wn + j * 8 + tq * 2;
            float v00 = acc[i][j][0], v01 = acc[i][j][1];
            float v10 = acc[i][j][2], v11 = acc[i][j][3];
            float bb0 = bias1[col], bb1 = bias1[col + 1];
            if (MODE == 2) { bb0 += bias2[col]; bb1 += bias2[col + 1]; }
            v00 = siluf(v00 + bb0); v01 = siluf(v01 + bb1);
            v10 = siluf(v10 + bb0); v11 = siluf(v11 + bb1);
            if (MODE == 1) {
                *(float2*)(Cf + (size_t)row * ldc + col)       = make_float2(v00, v01);
                *(float2*)(Cf + (size_t)(row + 8) * ldc + col) = make_float2(v10, v11);
            } else {
                __nv_bfloat16 h0, h1, h2, h3, l0, l1, l2, l3;
                split1(v00, h0, l0); split1(v01, h1, l1);
                split1(v10, h2, l2); split1(v11, h3, l3);
                *(uint32_t*)&Chi[(size_t)row * ldc + col]       = pk2(h0, h1);
                *(uint32_t*)&Clo[(size_t)row * ldc + col]       = pk2(l0, l1);
                *(uint32_t*)&Chi[(size_t)(row + 8) * ldc + col] = pk2(h2, h3);
                *(uint32_t*)&Clo[(size_t)(row + 8) * ldc + col] = pk2(l2, l3);
            }
        }
    }
}

// ---------------- head: out = G@Wh2 + bh2; log_s = tanh(out[:, :2]), b = out[:, 2:] ----------------
__global__ void head_kernel(const float* __restrict__ Wh2, const float* __restrict__ bh2,
                            float* __restrict__ out) {
    __shared__ float sw[4 * HID];
    int tid = threadIdx.x;
    for (int i = tid; i < 4 * HID; i += 256) {
        int jrow = i >> 2, k = i & 3;
        sw[k * HID + jrow] = Wh2[i];
    }
    __syncthreads();

    int warp = tid >> 5, lane = tid & 31;
    int n = blockIdx.x * 8 + warp;
    const float* g = &g_G[(size_t)n * HID];

    float o0 = 0.f, o1 = 0.f, o2 = 0.f, o3 = 0.f;
#pragma unroll 4
    for (int j = lane; j < HID; j += 32) {
        float gg = g[j];
        o0 += gg * sw[j];
        o1 += gg * sw[HID + j];
        o2 += gg * sw[2 * HID + j];
        o3 += gg * sw[3 * HID + j];
    }
#pragma unroll
    for (int off = 16; off; off >>= 1) {
        o0 += __shfl_down_sync(0xffffffffu, o0, off);
        o1 += __shfl_down_sync(0xffffffffu, o1, off);
        o2 += __shfl_down_sync(0xffffffffu, o2, off);
        o3 += __shfl_down_sync(0xffffffffu, o3, off);
    }
    if (lane == 0) {
        out[2 * n + 0] = tanhf(o0 + bh2[0]);
        out[2 * n + 1] = tanhf(o1 + bh2[1]);
        out[2 * NTOT + 2 * n + 0] = o2 + bh2[2];
        out[2 * NTOT + 2 * n + 1] = o3 + bh2[3];
    }
}

// ---------------- host ----------------
extern "C" void kernel_launch(void* const* d_in, const int* in_sizes, int n_in,
                              void* d_out, int out_size) {
    const float* X   = (const float*)d_in[0];
    const int*   EI  = (const int*)d_in[1];
    const float* W10 = (const float*)d_in[2];
    const float* b10 = (const float*)d_in[3];
    const float* W11 = (const float*)d_in[4];
    const float* b11 = (const float*)d_in[5];
    const float* W20 = (const float*)d_in[6];
    const float* b20 = (const float*)d_in[7];
    const float* W21 = (const float*)d_in[8];
    const float* b21 = (const float*)d_in[9];
    const float* Wh1 = (const float*)d_in[10];
    const float* bh1 = (const float*)d_in[11];
    const float* Wh2 = (const float*)d_in[12];
    const float* bh2 = (const float*)d_in[13];
    float* out = (float*)d_out;

    __nv_bfloat16 *pAhi, *pAlo, *pBhi, *pBlo, *pW2hi, *pW2lo, *pWhhi, *pWhlo;
    float* pG;
    cudaGetSymbolAddress((void**)&pAhi,  g_Ahi);
    cudaGetSymbolAddress((void**)&pAlo,  g_Alo);
    cudaGetSymbolAddress((void**)&pBhi,  g_Bhi);
    cudaGetSymbolAddress((void**)&pBlo,  g_Blo);
    cudaGetSymbolAddress((void**)&pW2hi, g_W2hi);
    cudaGetSymbolAddress((void**)&pW2lo, g_W2lo);
    cudaGetSymbolAddress((void**)&pWhhi, g_Whhi);
    cudaGetSymbolAddress((void**)&pWhlo, g_Whlo);
    cudaGetSymbolAddress((void**)&pG,    g_G);

    cudaFuncSetAttribute(hmma_gemm_kernel<1>, cudaFuncAttributeMaxDynamicSharedMemorySize, GEMM_SMEM);
    cudaFuncSetAttribute(hmma_gemm_kernel<2>, cudaFuncAttributeMaxDynamicSharedMemorySize, GEMM_SMEM);

    // graph norm + CSR
    zero_cnt_kernel<<<NNB / 256, 256>>>();
    hist_kernel<<<EDG / 256, 256>>>(EI);
    scan_kernel<<<1, 1024>>>();
    scatter_kernel<<<EDG / 256, 256>>>(EI);

    // weight preprocessing: stacked [W2_0; W2_1] (ldT=1024), Wh1 (ldT=512)
    dim3 wb(32, 8), wg(16, 16);
    split_w_kernel<<<wg, wb>>>(W20, pW2hi, pW2lo, 1024, 0);
    split_w_kernel<<<wg, wb>>>(W21, pW2hi, pW2lo, 1024, 512);
    split_w_kernel<<<wg, wb>>>(Wh1, pWhhi, pWhlo, 512, 0);

    // layer 1 -> split H1 in A cols 0:512
    layer1_kernel<<<NTOT / 8, 256>>>(X, W10, b10, W11, b11);

    // aggregate H1 -> A cols 512:1024
    aggH_kernel<<<NTOT, 128>>>();

    // layer 2: one K=1024 GEMM, fused (b20+b21)+silu, writes split H2
    dim3 gg(4, NTOT / 128);
    hmma_gemm_kernel<2><<<gg, 256, GEMM_SMEM>>>(pAhi, pAlo, pW2hi, pW2lo,
                                                nullptr, pBhi, pBlo, b20, b21,
                                                1024, 1024, 512, 1024);

    // head pre-GEMM: K=512, fused bh1+silu, writes fp32 G
    hmma_gemm_kernel<1><<<gg, 256, GEMM_SMEM>>>(pBhi, pBlo, pWhhi, pWhlo,
                                                pG, nullptr, nullptr, bh1, nullptr,
                                                512, 512, 512, 512);

    head_kernel<<<NTOT / 8, 256>>>(Wh2, bh2, out);
}

// round 5
// speedup vs baseline: 2.4391x; 1.0328x over previous
#include <cuda_runtime.h>
#include <cuda_bf16.h>
#include <math.h>
#include <stdint.h>

#define NBATCH 8
#define NNB    4096
#define NTOT   32768
#define EDG    65536
#define HID    512

// ---------------- scratch (device globals; no allocs allowed) ----------------
// A matrix for layer-2 GEMM: [M][1024] split bf16; cols 0:512 = H1, 512:1024 = agg(H1)
__device__ __nv_bfloat16 g_Ahi[(size_t)NTOT * 1024];   // 64 MB
__device__ __nv_bfloat16 g_Alo[(size_t)NTOT * 1024];   // 64 MB
// A matrix for head GEMM: [M][512] split bf16 (= H2)
__device__ __nv_bfloat16 g_Bhi[(size_t)NTOT * HID];    // 32 MB
__device__ __nv_bfloat16 g_Blo[(size_t)NTOT * HID];    // 32 MB
__device__ float g_hpart[(size_t)NTOT * 16];           // 2 MB  [m][tile 0..3][k 0..3]
// weights transposed [n][k], split
__device__ __nv_bfloat16 g_W2hi[HID * 1024];           // stacked [W2_0; W2_1]
__device__ __nv_bfloat16 g_W2lo[HID * 1024];
__device__ __nv_bfloat16 g_Whhi[HID * HID];            // Wh1
__device__ __nv_bfloat16 g_Whlo[HID * HID];
__device__ int   g_cnt[NNB];
__device__ int   g_rowptr[NNB + 1];
__device__ int   g_csr_src[EDG];
__device__ float g_csr_norm[EDG];
__device__ float g_dinv[NNB];

__device__ __forceinline__ float siluf(float x) {
    return x / (1.0f + expf(-x));
}

__device__ __forceinline__ uint32_t pk2(__nv_bfloat16 a, __nv_bfloat16 b) {
    return (uint32_t)__bfloat16_as_ushort(a) | ((uint32_t)__bfloat16_as_ushort(b) << 16);
}
__device__ __forceinline__ void unpk2(uint32_t u, float& a, float& b) {
    a = __bfloat162float(__ushort_as_bfloat16((unsigned short)(u & 0xffff)));
    b = __bfloat162float(__ushort_as_bfloat16((unsigned short)(u >> 16)));
}
__device__ __forceinline__ void split1(float v, __nv_bfloat16& h, __nv_bfloat16& l) {
    h = __float2bfloat16(v);
    l = __float2bfloat16(v - __bfloat162float(h));
}

// ---------------- PTX helpers ----------------
__device__ __forceinline__ uint32_t smem_u32(const void* p) {
    uint32_t a;
    asm("{ .reg .u64 t; cvta.to.shared.u64 t, %1; cvt.u32.u64 %0, t; }" : "=r"(a) : "l"(p));
    return a;
}

__device__ __forceinline__ void cp16(uint32_t dst, const void* src) {
    asm volatile("cp.async.cg.shared.global [%0], [%1], 16;" :: "r"(dst), "l"(src));
}
#define CP_COMMIT() asm volatile("cp.async.commit_group;" ::: "memory")
#define CP_WAIT(n)  asm volatile("cp.async.wait_group %0;" :: "n"(n) : "memory")

__device__ __forceinline__ void ldsm4(uint32_t* r, uint32_t addr) {
    asm volatile("ldmatrix.sync.aligned.m8n8.x4.shared.b16 {%0,%1,%2,%3}, [%4];"
                 : "=r"(r[0]), "=r"(r[1]), "=r"(r[2]), "=r"(r[3]) : "r"(addr));
}

__device__ __forceinline__ void mma16816(float* c, const uint32_t* a, uint32_t b0, uint32_t b1) {
    asm volatile(
        "mma.sync.aligned.m16n8k16.row.col.f32.bf16.bf16.f32 "
        "{%0,%1,%2,%3}, {%4,%5,%6,%7}, {%8,%9}, {%0,%1,%2,%3};"
        : "+f"(c[0]), "+f"(c[1]), "+f"(c[2]), "+f"(c[3])
        : "r"(a[0]), "r"(a[1]), "r"(a[2]), "r"(a[3]), "r"(b0), "r"(b1));
}

// ---------------- CSR build ----------------
__global__ void zero_cnt_kernel() {
    int i = blockIdx.x * blockDim.x + threadIdx.x;
    if (i < NNB) g_cnt[i] = 0;
}

__global__ void hist_kernel(const int* __restrict__ ei) {
    int e = blockIdx.x * blockDim.x + threadIdx.x;
    if (e < EDG) atomicAdd(&g_cnt[ei[EDG + e]], 1);
}

__global__ void scan_kernel() {
    __shared__ int s[1024];
    int tid = threadIdx.x;
    int c0 = g_cnt[tid * 4 + 0];
    int c1 = g_cnt[tid * 4 + 1];
    int c2 = g_cnt[tid * 4 + 2];
    int c3 = g_cnt[tid * 4 + 3];
    int local = c0 + c1 + c2 + c3;
    s[tid] = local;
    __syncthreads();
    for (int off = 1; off < 1024; off <<= 1) {
        int t = (tid >= off) ? s[tid - off] : 0;
        __syncthreads();
        s[tid] += t;
        __syncthreads();
    }
    int incl = s[tid];
    int excl = incl - local;
    g_rowptr[tid * 4 + 0] = excl;
    g_rowptr[tid * 4 + 1] = excl + c0;
    g_rowptr[tid * 4 + 2] = excl + c0 + c1;
    g_rowptr[tid * 4 + 3] = excl + c0 + c1 + c2;
    if (tid == 1023) g_rowptr[NNB] = incl;
    g_dinv[tid * 4 + 0] = rsqrtf((float)(c0 + 1));
    g_dinv[tid * 4 + 1] = rsqrtf((float)(c1 + 1));
    g_dinv[tid * 4 + 2] = rsqrtf((float)(c2 + 1));
    g_dinv[tid * 4 + 3] = rsqrtf((float)(c3 + 1));
    g_cnt[tid * 4 + 0] = 0;
    g_cnt[tid * 4 + 1] = 0;
    g_cnt[tid * 4 + 2] = 0;
    g_cnt[tid * 4 + 3] = 0;
}

__global__ void scatter_kernel(const int* __restrict__ ei) {
    int e = blockIdx.x * blockDim.x + threadIdx.x;
    if (e >= EDG) return;
    int s = ei[e];
    int d = ei[EDG + e];
    int pos = g_rowptr[d] + atomicAdd(&g_cnt[d], 1);
    g_csr_src[pos]  = s;
    g_csr_norm[pos] = g_dinv[s] * g_dinv[d];
}

// ---------------- layer 1: split bf16 H1 into g_Ahi/g_Alo cols 0:512 ----------------
__global__ void layer1_kernel(const float* __restrict__ X,
                              const float* __restrict__ W10, const float* __restrict__ b10,
                              const float* __restrict__ W11, const float* __restrict__ b11) {
    __shared__ float sW[5 * HID];
    int tid = threadIdx.x;
    for (int i = tid; i < HID; i += 256) {
        sW[i]           = W10[i];
        sW[HID + i]     = W10[HID + i];
        sW[2 * HID + i] = W11[i];
        sW[3 * HID + i] = W11[HID + i];
        sW[4 * HID + i] = b10[i] + b11[i];
    }
    __syncthreads();

    int warp = tid >> 5, lane = tid & 31;
    int n = blockIdx.x * 8 + warp;
    int v = n & (NNB - 1);
    int base = n & ~(NNB - 1);

    float x0 = X[2 * n], x1 = X[2 * n + 1];
    float a0 = 0.f, a1 = 0.f;
    int r0 = g_rowptr[v], r1 = g_rowptr[v + 1];
    for (int e = r0 + lane; e < r1; e += 32) {
        int s = g_csr_src[e];
        float nm = g_csr_norm[e];
        a0 += nm * X[2 * (base + s)];
        a1 += nm * X[2 * (base + s) + 1];
    }
#pragma unroll
    for (int off = 16; off; off >>= 1) {
        a0 += __shfl_down_sync(0xffffffffu, a0, off);
        a1 += __shfl_down_sync(0xffffffffu, a1, off);
    }
    a0 = __shfl_sync(0xffffffffu, a0, 0);
    a1 = __shfl_sync(0xffffffffu, a1, 0);
    float dv = g_dinv[v];
    float sn = dv * dv;
    a0 += sn * x0;
    a1 += sn * x1;

    __nv_bfloat16* oh = &g_Ahi[(size_t)n * 1024];
    __nv_bfloat16* ol = &g_Alo[(size_t)n * 1024];
#pragma unroll 4
    for (int j = lane; j < HID; j += 32) {
        float h = x0 * sW[j] + x1 * sW[HID + j] + a0 * sW[2 * HID + j] + a1 * sW[3 * HID + j] + sW[4 * HID + j];
        float sv = siluf(h);
        __nv_bfloat16 hh, ll;
        split1(sv, hh, ll);
        oh[j] = hh;
        ol[j] = ll;
    }
}

// ---------------- aggregate H1 -> cols 512:1024 ----------------
__global__ void aggH_kernel() {
    int n = blockIdx.x;
    int tid = threadIdx.x;
    int v = n & (NNB - 1);
    int base = n & ~(NNB - 1);
    int j = tid * 4;

    float acc0 = 0.f, acc1 = 0.f, acc2 = 0.f, acc3 = 0.f;
    int r0 = g_rowptr[v], r1 = g_rowptr[v + 1];
    for (int e = r0; e < r1; e++) {
        int s = g_csr_src[e];
        float nm = g_csr_norm[e];
        size_t ro = (size_t)(base + s) * 1024 + j;
        uint2 uh = *(const uint2*)&g_Ahi[ro];
        uint2 ul = *(const uint2*)&g_Alo[ro];
        float h0, h1, h2, h3, l0, l1, l2, l3;
        unpk2(uh.x, h0, h1); unpk2(uh.y, h2, h3);
        unpk2(ul.x, l0, l1); unpk2(ul.y, l2, l3);
        acc0 += nm * (h0 + l0);
        acc1 += nm * (h1 + l1);
        acc2 += nm * (h2 + l2);
        acc3 += nm * (h3 + l3);
    }
    {
        float dv = g_dinv[v];
        float sn = dv * dv;
        size_t ro = (size_t)n * 1024 + j;
        uint2 uh = *(const uint2*)&g_Ahi[ro];
        uint2 ul = *(const uint2*)&g_Alo[ro];
        float h0, h1, h2, h3, l0, l1, l2, l3;
        unpk2(uh.x, h0, h1); unpk2(uh.y, h2, h3);
        unpk2(ul.x, l0, l1); unpk2(ul.y, l2, l3);
        acc0 += sn * (h0 + l0);
        acc1 += sn * (h1 + l1);
        acc2 += sn * (h2 + l2);
        acc3 += sn * (h3 + l3);
    }
    __nv_bfloat16 h0, h1, h2, h3, l0, l1, l2, l3;
    split1(acc0, h0, l0); split1(acc1, h1, l1);
    split1(acc2, h2, l2); split1(acc3, h3, l3);
    size_t wo = (size_t)n * 1024 + 512 + j;
    *(uint2*)&g_Ahi[wo] = make_uint2(pk2(h0, h1), pk2(h2, h3));
    *(uint2*)&g_Alo[wo] = make_uint2(pk2(l0, l1), pk2(l2, l3));
}

// ---------------- transpose + split weight ----------------
__global__ void split_w_kernel(const float* __restrict__ W,
                               __nv_bfloat16* __restrict__ Thi, __nv_bfloat16* __restrict__ Tlo,
                               int ldT, int koff) {
    __shared__ float tile[32][33];
    int bn = blockIdx.x * 32, bk = blockIdx.y * 32;
    int tx = threadIdx.x;
    for (int ty = threadIdx.y; ty < 32; ty += 8)
        tile[ty][tx] = W[(size_t)(bk + ty) * HID + bn + tx];
    __syncthreads();
    for (int ty = threadIdx.y; ty < 32; ty += 8) {
        float x = tile[tx][ty];
        __nv_bfloat16 h, l;
        split1(x, h, l);
        size_t o = (size_t)(bn + ty) * ldT + koff + bk + tx;
        Thi[o] = h;
        Tlo[o] = l;
    }
}

// ---------------- HMMA split-precision GEMM ----------------
// MODE 1 (head): silu(acc+bias1) projected against Wh2 tile -> per-tile partials Cf[m][bx][4]
// MODE 2: (Chi,Clo) = split(silu(acc + bias1 + bias2))
#define TROW_B   80
#define TILE_B   (128 * TROW_B)          // 10240
#define STAGE_B  (4 * TILE_B)            // 40960
#define SWH2_OFF (2 * STAGE_B)           // 81920, 2KB: Wh2 tile [128][4]
#define SPART_OFF (SWH2_OFF + 2048)      // 83968, 8KB: s_part[128][4 slots][4]
#define GEMM_SMEM_2 (2 * STAGE_B)                // 81920
#define GEMM_SMEM_1 (SPART_OFF + 8192)           // 92160

__device__ __forceinline__ void load_stage(uint32_t sb, uint32_t stg,
                                           const __nv_bfloat16* Ahi, const __nv_bfloat16* Alo,
                                           const __nv_bfloat16* Bhi, const __nv_bfloat16* Blo,
                                           int m0, int n0, int kc, int lda, int ldb, int tid) {
#pragma unroll
    for (int i = 0; i < 2; i++) {
        int idx = tid + i * 256;
        int r = idx >> 2, g = idx & 3;
        uint32_t doff = stg + (uint32_t)(r * TROW_B + g * 16);
        size_t asrc = (size_t)(m0 + r) * lda + kc + g * 8;
        size_t bsrc = (size_t)(n0 + r) * ldb + kc + g * 8;
        cp16(sb + doff,                Ahi + asrc);
        cp16(sb + doff + TILE_B,       Alo + asrc);
        cp16(sb + doff + 2 * TILE_B,   Bhi + bsrc);
        cp16(sb + doff + 3 * TILE_B,   Blo + bsrc);
    }
}

template <int MODE>
__global__ void __launch_bounds__(256, 2)
hmma_gemm_kernel(const __nv_bfloat16* __restrict__ Ahi, const __nv_bfloat16* __restrict__ Alo,
                 const __nv_bfloat16* __restrict__ Bhi, const __nv_bfloat16* __restrict__ Blo,
                 float* __restrict__ Cf,
                 __nv_bfloat16* __restrict__ Chi, __nv_bfloat16* __restrict__ Clo,
                 const float* __restrict__ bias1, const float* __restrict__ bias2,
                 const float* __restrict__ Wproj,
                 int lda, int ldb, int ldc, int K) {
    extern __shared__ __align__(128) char smem[];
    uint32_t sb = smem_u32(smem);
    int tid = threadIdx.x, wid = tid >> 5, lane = tid & 31;
    int n0 = blockIdx.x * 128;
    int m0 = blockIdx.y * 128;
    int wm = (wid & 1) * 64;
    int wn = (wid >> 1) * 32;

    float acc[4][4][4];
#pragma unroll
    for (int i = 0; i < 4; i++)
#pragma unroll
        for (int j = 0; j < 4; j++)
#pragma unroll
            for (int q = 0; q < 4; q++) acc[i][j][q] = 0.f;

    int lrow = lane & 15;
    uint32_t kByte = (uint32_t)(lane >> 4) * 16;
    uint32_t aRow[4], bRow[2];
#pragma unroll
    for (int i = 0; i < 4; i++) aRow[i] = (uint32_t)((wm + i * 16 + lrow) * TROW_B) + kByte;
#pragma unroll
    for (int p = 0; p < 2; p++) bRow[p] = (uint32_t)((wn + p * 16 + lrow) * TROW_B) + kByte;

    const int nt = K / 32;

    load_stage(sb, 0, Ahi, Alo, Bhi, Blo, m0, n0, 0, lda, ldb, tid);
    CP_COMMIT();

    for (int t = 0; t < nt; t++) {
        uint32_t stg = (uint32_t)(t & 1) * STAGE_B;
        if (t + 1 < nt) {
            load_stage(sb, (uint32_t)((t + 1) & 1) * STAGE_B, Ahi, Alo, Bhi, Blo, m0, n0,
                       (t + 1) * 32, lda, ldb, tid);
            CP_COMMIT();
            CP_WAIT(1);
        } else {
            CP_WAIT(0);
        }
        __syncthreads();

        uint32_t aHiB = sb + stg, aLoB = aHiB + TILE_B;
        uint32_t bHiB = aHiB + 2 * TILE_B, bLoB = aHiB + 3 * TILE_B;

#pragma unroll
        for (int kk = 0; kk < 2; kk++) {
            uint32_t ko = (uint32_t)kk * 32;
            uint32_t ah[4][4], bh[2][4], tf[4][4];
#pragma unroll
            for (int i = 0; i < 4; i++) ldsm4(ah[i], aHiB + aRow[i] + ko);
#pragma unroll
            for (int p = 0; p < 2; p++) ldsm4(bh[p], bHiB + bRow[p] + ko);
#pragma unroll
            for (int i = 0; i < 4; i++)
#pragma unroll
                for (int p = 0; p < 2; p++) {
                    mma16816(acc[i][2 * p],     ah[i], bh[p][0], bh[p][2]);
                    mma16816(acc[i][2 * p + 1], ah[i], bh[p][1], bh[p][3]);
                }
#pragma unroll
            for (int p = 0; p < 2; p++) ldsm4(tf[p], bLoB + bRow[p] + ko);
#pragma unroll
            for (int i = 0; i < 4; i++)
#pragma unroll
                for (int p = 0; p < 2; p++) {
                    mma16816(acc[i][2 * p],     ah[i], tf[p][0], tf[p][2]);
                    mma16816(acc[i][2 * p + 1], ah[i], tf[p][1], tf[p][3]);
                }
#pragma unroll
            for (int i = 0; i < 4; i++) ldsm4(tf[i], aLoB + aRow[i] + ko);
#pragma unroll
            for (int i = 0; i < 4; i++)
#pragma unroll
                for (int p = 0; p < 2; p++) {
                    mma16816(acc[i][2 * p],     tf[i], bh[p][0], bh[p][2]);
                    mma16816(acc[i][2 * p + 1], tf[i], bh[p][1], bh[p][3]);
                }
        }
        __syncthreads();
    }

    int quad = lane >> 2, tq = lane & 3;

    if (MODE == 2) {
#pragma unroll
        for (int i = 0; i < 4; i++) {
            int row = m0 + wm + i * 16 + quad;
#pragma unroll
            for (int j = 0; j < 4; j++) {
                int col = n0 + wn + j * 8 + tq * 2;
                float v00 = acc[i][j][0], v01 = acc[i][j][1];
                float v10 = acc[i][j][2], v11 = acc[i][j][3];
                float bb0 = bias1[col] + bias2[col];
                float bb1 = bias1[col + 1] + bias2[col + 1];
                v00 = siluf(v00 + bb0); v01 = siluf(v01 + bb1);
                v10 = siluf(v10 + bb0); v11 = siluf(v11 + bb1);
                __nv_bfloat16 h0, h1, h2, h3, l0, l1, l2, l3;
                split1(v00, h0, l0); split1(v01, h1, l1);
                split1(v10, h2, l2); split1(v11, h3, l3);
                *(uint32_t*)&Chi[(size_t)row * ldc + col]       = pk2(h0, h1);
                *(uint32_t*)&Clo[(size_t)row * ldc + col]       = pk2(l0, l1);
                *(uint32_t*)&Chi[(size_t)(row + 8) * ldc + col] = pk2(h2, h3);
                *(uint32_t*)&Clo[(size_t)(row + 8) * ldc + col] = pk2(l2, l3);
            }
        }
    } else {
        // MODE 1: fused head projection.
        // sWh2[c][k] = Wproj[(n0+c)*4 + k] for the 128 cols of this tile.
        float4* sWh2 = (float4*)(smem + SWH2_OFF);
        float*  sPart = (float*)(smem + SPART_OFF);  // [128 rows][4 slots][4]
        if (tid < 128) sWh2[tid] = ((const float4*)Wproj)[n0 + tid];
        __syncthreads();

        int slot = wid >> 1;  // warp pair (2s, 2s+1) covers disjoint rows for slot s
#pragma unroll
        for (int i = 0; i < 4; i++) {
            float p0[4] = {0.f, 0.f, 0.f, 0.f};
            float p1[4] = {0.f, 0.f, 0.f, 0.f};
#pragma unroll
            for (int j = 0; j < 4; j++) {
                int c = wn + j * 8 + tq * 2;  // local col in tile
                float bb0 = bias1[n0 + c], bb1 = bias1[n0 + c + 1];
                float v00 = siluf(acc[i][j][0] + bb0);
                float v01 = siluf(acc[i][j][1] + bb1);
                float v10 = siluf(acc[i][j][2] + bb0);
                float v11 = siluf(acc[i][j][3] + bb1);
                float4 w0 = sWh2[c], w1 = sWh2[c + 1];
                p0[0] += v00 * w0.x + v01 * w1.x;
                p0[1] += v00 * w0.y + v01 * w1.y;
                p0[2] += v00 * w0.z + v01 * w1.z;
                p0[3] += v00 * w0.w + v01 * w1.w;
                p1[0] += v10 * w0.x + v11 * w1.x;
                p1[1] += v10 * w0.y + v11 * w1.y;
                p1[2] += v10 * w0.z + v11 * w1.z;
                p1[3] += v10 * w0.w + v11 * w1.w;
            }
            // reduce over tq (4 lanes within each quad group)
#pragma unroll
            for (int k = 0; k < 4; k++) {
                p0[k] += __shfl_xor_sync(0xffffffffu, p0[k], 1);
                p0[k] += __shfl_xor_sync(0xffffffffu, p0[k], 2);
                p1[k] += __shfl_xor_sync(0xffffffffu, p1[k], 1);
                p1[k] += __shfl_xor_sync(0xffffffffu, p1[k], 2);
            }
            if (tq == 0) {
                int r = wm + i * 16 + quad;
#pragma unroll
                for (int k = 0; k < 4; k++) {
                    sPart[(r * 4 + slot) * 4 + k]       = p0[k];
                    sPart[((r + 8) * 4 + slot) * 4 + k] = p1[k];
                }
            }
        }
        __syncthreads();
        if (tid < 128) {
            float4 s = make_float4(0.f, 0.f, 0.f, 0.f);
#pragma unroll
            for (int sl = 0; sl < 4; sl++) {
                float4 v = *(float4*)&sPart[(tid * 4 + sl) * 4];
                s.x += v.x; s.y += v.y; s.z += v.z; s.w += v.w;
            }
            ((float4*)Cf)[(size_t)(m0 + tid) * 4 + blockIdx.x] = s;
        }
    }
}

// ---------------- finish: sum head partials, tanh/store ----------------
__global__ void finish_kernel(const float* __restrict__ hp, const float* __restrict__ bh2,
                              float* __restrict__ out) {
    int n = blockIdx.x * 256 + threadIdx.x;
    const float4* v = (const float4*)hp + (size_t)n * 4;
    float4 a = v[0], b = v[1], c = v[2], d = v[3];
    float o0 = a.x + b.x + c.x + d.x + bh2[0];
    float o1 = a.y + b.y + c.y + d.y + bh2[1];
    float o2 = a.z + b.z + c.z + d.z + bh2[2];
    float o3 = a.w + b.w + c.w + d.w + bh2[3];
    out[2 * n + 0] = tanhf(o0);
    out[2 * n + 1] = tanhf(o1);
    out[2 * NTOT + 2 * n + 0] = o2;
    out[2 * NTOT + 2 * n + 1] = o3;
}

// ---------------- host ----------------
extern "C" void kernel_launch(void* const* d_in, const int* in_sizes, int n_in,
                              void* d_out, int out_size) {
    const float* X   = (const float*)d_in[0];
    const int*   EI  = (const int*)d_in[1];
    const float* W10 = (const float*)d_in[2];
    const float* b10 = (const float*)d_in[3];
    const float* W11 = (const float*)d_in[4];
    const float* b11 = (const float*)d_in[5];
    const float* W20 = (const float*)d_in[6];
    const float* b20 = (const float*)d_in[7];
    const float* W21 = (const float*)d_in[8];
    const float* b21 = (const float*)d_in[9];
    const float* Wh1 = (const float*)d_in[10];
    const float* bh1 = (const float*)d_in[11];
    const float* Wh2 = (const float*)d_in[12];
    const float* bh2 = (const float*)d_in[13];
    float* out = (float*)d_out;

    __nv_bfloat16 *pAhi, *pAlo, *pBhi, *pBlo, *pW2hi, *pW2lo, *pWhhi, *pWhlo;
    float* pHp;
    cudaGetSymbolAddress((void**)&pAhi,  g_Ahi);
    cudaGetSymbolAddress((void**)&pAlo,  g_Alo);
    cudaGetSymbolAddress((void**)&pBhi,  g_Bhi);
    cudaGetSymbolAddress((void**)&pBlo,  g_Blo);
    cudaGetSymbolAddress((void**)&pW2hi, g_W2hi);
    cudaGetSymbolAddress((void**)&pW2lo, g_W2lo);
    cudaGetSymbolAddress((void**)&pWhhi, g_Whhi);
    cudaGetSymbolAddress((void**)&pWhlo, g_Whlo);
    cudaGetSymbolAddress((void**)&pHp,   g_hpart);

    cudaFuncSetAttribute(hmma_gemm_kernel<1>, cudaFuncAttributeMaxDynamicSharedMemorySize, GEMM_SMEM_1);
    cudaFuncSetAttribute(hmma_gemm_kernel<2>, cudaFuncAttributeMaxDynamicSharedMemorySize, GEMM_SMEM_2);

    // graph norm + CSR
    zero_cnt_kernel<<<NNB / 256, 256>>>();
    hist_kernel<<<EDG / 256, 256>>>(EI);
    scan_kernel<<<1, 1024>>>();
    scatter_kernel<<<EDG / 256, 256>>>(EI);

    // weight preprocessing
    dim3 wb(32, 8), wg(16, 16);
    split_w_kernel<<<wg, wb>>>(W20, pW2hi, pW2lo, 1024, 0);
    split_w_kernel<<<wg, wb>>>(W21, pW2hi, pW2lo, 1024, 512);
    split_w_kernel<<<wg, wb>>>(Wh1, pWhhi, pWhlo, 512, 0);

    // layer 1 -> split H1 in A cols 0:512
    layer1_kernel<<<NTOT / 8, 256>>>(X, W10, b10, W11, b11);

    // aggregate H1 -> A cols 512:1024
    aggH_kernel<<<NTOT, 128>>>();

    // layer 2: one K=1024 GEMM, fused (b20+b21)+silu, writes split H2
    dim3 gg(4, NTOT / 128);
    hmma_gemm_kernel<2><<<gg, 256, GEMM_SMEM_2>>>(pAhi, pAlo, pW2hi, pW2lo,
                                                  nullptr, pBhi, pBlo, b20, b21, nullptr,
                                                  1024, 1024, 512, 1024);

    // head GEMM: K=512, fused bh1+silu+projection(Wh2) -> partials
    hmma_gemm_kernel<1><<<gg, 256, GEMM_SMEM_1>>>(pBhi, pBlo, pWhhi, pWhlo,
                                                  pHp, nullptr, nullptr, bh1, nullptr, Wh2,
                                                  512, 512, 512, 512);

    finish_kernel<<<NTOT / 256, 256>>>(pHp, bh2, out);
}